// round 7
// baseline (speedup 1.0000x reference)
#include <cuda_runtime.h>
#include <cstdint>
#include <cstddef>

// ---------------------------------------------------------------------------
// BinaryDense: out[N,F] = inputs[N,D] @ w_bin[D,F],  N=2^20, D=F=128
// w_bin = 2*bernoulli(partitionable-threefry(key(seed)), hard_sigmoid(W)) - 1
// tf32 mma.sync GEMM. 512 threads/CTA (16 warps, 4m x 4n), 32 acc regs/thread.
// B held as sign-bit registers, A via ldmatrix.x4, triple-buffered cp.async.
// ---------------------------------------------------------------------------

#define PAD        132                      // floats per padded SMEM row
#define ABUF_FLTS  (128 * PAD)              // 16896 floats = 67584 B
#define SMEM_TOTAL (3 * ABUF_FLTS * 4)      // 3 A buffers = 202752 B

// w_bin image, [f][d] row-major, values exactly +1.0f / -1.0f
static __device__ float g_B[16384];

// --------------------------- w_bin precompute ------------------------------
// Partitionable threefry2x32 (modern JAX default):
//   key = (0, seed); ctr = (0, idx); bits = out0 ^ out1
//   u = bitcast((bits>>9)|0x3f800000) - 1
//   w_bin = (u < clip((w+1)*0.5,0,1)) ? +1 : -1    (sign(w) if !is_training)

__device__ __forceinline__ uint32_t rotl32(uint32_t x, int r) {
    return (x << r) | (x >> (32 - r));
}

__global__ void wbin_kernel(const float* __restrict__ w,
                            const int* __restrict__ seedp,
                            const int* __restrict__ trainp) {
    int idx = blockIdx.x * blockDim.x + threadIdx.x;   // (d, f) row-major
    int d = idx >> 7;
    int f = idx & 127;
    float wv = w[idx];
    float bin;
    if (*trainp) {
        uint32_t k0 = 0u, k1 = (uint32_t)(*seedp);
        uint32_t x0 = 0u;                  // counter hi word
        uint32_t x1 = (uint32_t)idx;       // counter lo word
        uint32_t ks[3] = { k0, k1, k0 ^ k1 ^ 0x1BD11BDAu };
        x0 += ks[0];
        x1 += ks[1];
        const int rot[2][4] = { {13, 15, 26, 6}, {17, 29, 16, 24} };
        #pragma unroll
        for (int i = 0; i < 5; i++) {
            #pragma unroll
            for (int j = 0; j < 4; j++) {
                x0 += x1;
                x1 = rotl32(x1, rot[i & 1][j]);
                x1 ^= x0;
            }
            x0 += ks[(i + 1) % 3];
            x1 += ks[(i + 2) % 3] + (uint32_t)(i + 1);
        }
        uint32_t bits = x0 ^ x1;           // partitionable fold
        float u = __uint_as_float((bits >> 9) | 0x3f800000u) - 1.0f;
        float p = fminf(fmaxf((wv + 1.0f) * 0.5f, 0.0f), 1.0f);
        bin = (u < p) ? 1.0f : -1.0f;
    } else {
        bin = (wv > 0.0f) ? 1.0f : -1.0f;
    }
    g_B[f * 128 + d] = bin;   // transposed: [f][d]
}

// ------------------------------- GEMM --------------------------------------

__device__ __forceinline__ uint32_t smem_u32(const void* p) {
    uint32_t a;
    asm("{ .reg .u64 t; cvta.to.shared.u64 t, %1; cvt.u32.u64 %0, t; }"
        : "=r"(a) : "l"(p));
    return a;
}

__device__ __forceinline__ uint32_t f2tf32(uint32_t xbits) {
    uint32_t r;
    asm("cvt.rna.tf32.f32 %0, %1;" : "=r"(r) : "f"(__uint_as_float(xbits)));
    return r;
}

__device__ __forceinline__ void mma_tf32(float* d, uint32_t a0, uint32_t a1,
                                         uint32_t a2, uint32_t a3,
                                         uint32_t b0, uint32_t b1) {
    asm volatile(
        "mma.sync.aligned.m16n8k8.row.col.f32.tf32.tf32.f32 "
        "{%0,%1,%2,%3}, {%4,%5,%6,%7}, {%8,%9}, {%0,%1,%2,%3};"
        : "+f"(d[0]), "+f"(d[1]), "+f"(d[2]), "+f"(d[3])
        : "r"(a0), "r"(a1), "r"(a2), "r"(a3), "r"(b0), "r"(b1));
}

__device__ __forceinline__ void ldsm_x4(uint32_t* r, uint32_t addr) {
    asm volatile("ldmatrix.sync.aligned.m8n8.x4.shared.b16 {%0,%1,%2,%3}, [%4];"
                 : "=r"(r[0]), "=r"(r[1]), "=r"(r[2]), "=r"(r[3]) : "r"(addr));
}

// One 128x128-float A tile (64 KB) -> padded SMEM buffer, 16B cp.async chunks.
// 512 threads: 4096 chunks, 8 per thread.
__device__ __forceinline__ void issue_a(uint32_t sbase, const float* __restrict__ A,
                                        int tile, int tid) {
    const char* g = (const char*)(A + (size_t)tile * 16384);
    #pragma unroll
    for (int j = 0; j < 8; j++) {
        int id = tid + j * 512;            // 4096 chunks of 16 B
        int m  = id >> 5;
        int k4 = id & 31;
        uint32_t soff = sbase + (uint32_t)(m * PAD + k4 * 4) * 4u;
        asm volatile("cp.async.cg.shared.global [%0], [%1], 16;"
                     :: "r"(soff), "l"(g + (size_t)m * 512 + (size_t)k4 * 16)
                     : "memory");
    }
}

__global__ void __launch_bounds__(512, 1)
gemm_kernel(const float* __restrict__ A, float* __restrict__ out, int n_tiles) {
    extern __shared__ float smem[];
    int tid  = threadIdx.x;
    int wid  = tid >> 5;
    int lane = tid & 31;
    int wm   = wid >> 2;          // 0..3 -> 32-row quarter
    int wn   = wid & 3;           // 0..3 -> 32-col quarter
    int r    = lane >> 2;         // fragment row group 0..7
    int c    = lane & 3;          // fragment col group 0..3

    uint32_t sbase[3];
    sbase[0] = smem_u32(smem);
    sbase[1] = sbase[0] + ABUF_FLTS * 4;
    sbase[2] = sbase[0] + 2 * ABUF_FLTS * 4;

    // ---- pack B fragment sign bits: bw[nf] bit j = sign(B^T[n][c+4j]) ----
    uint32_t bw[4];
    #pragma unroll
    for (int nf = 0; nf < 4; nf++) {
        const float* bp = g_B + (size_t)((wn * 32 + nf * 8 + r) * 128 + c);
        uint32_t w = 0;
        #pragma unroll
        for (int j = 0; j < 32; j++)
            w |= (__float_as_uint(bp[4 * j]) >> 31) << j;
        bw[nf] = w;
    }

    int grid  = (int)gridDim.x;
    int tile0 = (int)blockIdx.x;

    // ---- prologue: fill 3 A buffers ----
    issue_a(sbase[0], A, tile0, tid);
    asm volatile("cp.async.commit_group;" ::: "memory");
    if (tile0 + grid < n_tiles) issue_a(sbase[1], A, tile0 + grid, tid);
    asm volatile("cp.async.commit_group;" ::: "memory");
    if (tile0 + 2 * grid < n_tiles) issue_a(sbase[2], A, tile0 + 2 * grid, tid);
    asm volatile("cp.async.commit_group;" ::: "memory");

    // ldmatrix lane address (byte offset within an A buffer):
    // block j of x4: rows wm*32 + mf*16 + (j&1)*8 + (lane&7), col (j>>1)*4 floats
    uint32_t arow = (uint32_t)(wm * 32 + ((lane >> 3) & 1) * 8 + (lane & 7));
    uint32_t aoff = (arow * PAD + (uint32_t)((lane >> 4) * 4)) * 4u;

    int it = 0;
    for (int tile = tile0; tile < n_tiles; tile += grid, it++) {
        uint32_t abase = sbase[it % 3];

        asm volatile("cp.async.wait_group 2;" ::: "memory");
        __syncthreads();

        float acc[2][4][4];
        #pragma unroll
        for (int mf = 0; mf < 2; mf++)
            #pragma unroll
            for (int nf = 0; nf < 4; nf++)
                #pragma unroll
                for (int q = 0; q < 4; q++) acc[mf][nf][q] = 0.0f;

        uint32_t addr0 = abase + aoff;                  // mf = 0
        uint32_t addr1 = addr0 + 16u * PAD * 4u;        // mf = 1

        #pragma unroll
        for (int q = 0; q < 16; q++) {                  // k0 = 8q
            uint32_t a0[4], a1[4];
            ldsm_x4(a0, addr0 + (uint32_t)q * 32u);
            ldsm_x4(a1, addr1 + (uint32_t)q * 32u);
            #pragma unroll
            for (int t = 0; t < 4; t++) { a0[t] = f2tf32(a0[t]); a1[t] = f2tf32(a1[t]); }

            #pragma unroll
            for (int nf = 0; nf < 4; nf++) {
                uint32_t b0 = 0x3F800000u | ((bw[nf] << (31 - 2 * q)) & 0x80000000u);
                uint32_t b1 = 0x3F800000u | ((bw[nf] << (30 - 2 * q)) & 0x80000000u);
                mma_tf32(acc[0][nf], a0[0], a0[1], a0[2], a0[3], b0, b1);
                mma_tf32(acc[1][nf], a1[0], a1[1], a1[2], a1[3], b0, b1);
            }
        }

        __syncthreads();   // all warps done reading this A buffer

        int nt = tile + 3 * grid;
        if (nt < n_tiles) issue_a(abase, A, nt, tid);
        asm volatile("cp.async.commit_group;" ::: "memory");

        // ---- epilogue: streaming stores ----
        float* obase = out + ((size_t)tile * 128 + (size_t)(wm * 32)) * 128 + wn * 32;
        #pragma unroll
        for (int mf = 0; mf < 2; mf++) {
            #pragma unroll
            for (int nf = 0; nf < 4; nf++) {
                float* p = obase + (size_t)(mf * 16 + r) * 128 + nf * 8 + c * 2;
                __stcs((float2*)p,             make_float2(acc[mf][nf][0], acc[mf][nf][1]));
                __stcs((float2*)(p + 8 * 128), make_float2(acc[mf][nf][2], acc[mf][nf][3]));
            }
        }
    }
}

// ------------------------------ launch -------------------------------------

extern "C" void kernel_launch(void* const* d_in, const int* in_sizes, int n_in,
                              void* d_out, int out_size) {
    const float* A       = (const float*)d_in[0];
    const float* W       = (const float*)d_in[1];
    const int*   seed    = (const int*)d_in[2];
    const int*   istrain = (const int*)d_in[3];
    float* out = (float*)d_out;

    int N = in_sizes[0] / 128;
    int n_tiles = N / 128;                 // 8192

    wbin_kernel<<<64, 256>>>(W, seed, istrain);

    int sms = 148;
    cudaDeviceGetAttribute(&sms, cudaDevAttrMultiProcessorCount, 0);
    if (sms > n_tiles) sms = n_tiles;

    cudaFuncSetAttribute(gemm_kernel, cudaFuncAttributeMaxDynamicSharedMemorySize, SMEM_TOTAL);
    gemm_kernel<<<sms, 512, SMEM_TOTAL>>>(A, out, n_tiles);
}

// round 8
// speedup vs baseline: 1.0935x; 1.0935x over previous
#include <cuda_runtime.h>
#include <cstdint>
#include <cstddef>

// ---------------------------------------------------------------------------
// BinaryDense: out[N,F] = inputs[N,D] @ w_bin[D,F],  N=2^20, D=F=128
// w_bin = 2*bernoulli(partitionable-threefry(key(seed)), hard_sigmoid(W)) - 1
// tf32 mma.sync GEMM. 2 CTAs/SM (tile M=64) to fill latency bubbles.
// B held as sign-bit registers, A via ldmatrix.x4, triple-buffered cp.async.
// ---------------------------------------------------------------------------

#define PAD        132                      // floats per padded SMEM row
#define TM         64                       // CTA tile rows
#define ABUF_FLTS  (TM * PAD)               // 8448 floats = 33792 B
#define SMEM_TOTAL (3 * ABUF_FLTS * 4)      // 3 A buffers = 101376 B per CTA

// w_bin image, [f][d] row-major, values exactly +1.0f / -1.0f
static __device__ float g_B[16384];

// --------------------------- w_bin precompute ------------------------------
// Partitionable threefry2x32 (modern JAX default):
//   key = (0, seed); ctr = (0, idx); bits = out0 ^ out1
//   u = bitcast((bits>>9)|0x3f800000) - 1
//   w_bin = (u < clip((w+1)*0.5,0,1)) ? +1 : -1    (sign(w) if !is_training)

__device__ __forceinline__ uint32_t rotl32(uint32_t x, int r) {
    return (x << r) | (x >> (32 - r));
}

__global__ void wbin_kernel(const float* __restrict__ w,
                            const int* __restrict__ seedp,
                            const int* __restrict__ trainp) {
    int idx = blockIdx.x * blockDim.x + threadIdx.x;   // (d, f) row-major
    int d = idx >> 7;
    int f = idx & 127;
    float wv = w[idx];
    float bin;
    if (*trainp) {
        uint32_t k0 = 0u, k1 = (uint32_t)(*seedp);
        uint32_t x0 = 0u;                  // counter hi word
        uint32_t x1 = (uint32_t)idx;       // counter lo word
        uint32_t ks[3] = { k0, k1, k0 ^ k1 ^ 0x1BD11BDAu };
        x0 += ks[0];
        x1 += ks[1];
        const int rot[2][4] = { {13, 15, 26, 6}, {17, 29, 16, 24} };
        #pragma unroll
        for (int i = 0; i < 5; i++) {
            #pragma unroll
            for (int j = 0; j < 4; j++) {
                x0 += x1;
                x1 = rotl32(x1, rot[i & 1][j]);
                x1 ^= x0;
            }
            x0 += ks[(i + 1) % 3];
            x1 += ks[(i + 2) % 3] + (uint32_t)(i + 1);
        }
        uint32_t bits = x0 ^ x1;           // partitionable fold
        float u = __uint_as_float((bits >> 9) | 0x3f800000u) - 1.0f;
        float p = fminf(fmaxf((wv + 1.0f) * 0.5f, 0.0f), 1.0f);
        bin = (u < p) ? 1.0f : -1.0f;
    } else {
        bin = (wv > 0.0f) ? 1.0f : -1.0f;
    }
    g_B[f * 128 + d] = bin;   // transposed: [f][d]
}

// ------------------------------- GEMM --------------------------------------

__device__ __forceinline__ uint32_t smem_u32(const void* p) {
    uint32_t a;
    asm("{ .reg .u64 t; cvta.to.shared.u64 t, %1; cvt.u32.u64 %0, t; }"
        : "=r"(a) : "l"(p));
    return a;
}

__device__ __forceinline__ uint32_t f2tf32(uint32_t xbits) {
    uint32_t r;
    asm("cvt.rna.tf32.f32 %0, %1;" : "=r"(r) : "f"(__uint_as_float(xbits)));
    return r;
}

__device__ __forceinline__ void mma_tf32(float* d, uint32_t a0, uint32_t a1,
                                         uint32_t a2, uint32_t a3,
                                         uint32_t b0, uint32_t b1) {
    asm volatile(
        "mma.sync.aligned.m16n8k8.row.col.f32.tf32.tf32.f32 "
        "{%0,%1,%2,%3}, {%4,%5,%6,%7}, {%8,%9}, {%0,%1,%2,%3};"
        : "+f"(d[0]), "+f"(d[1]), "+f"(d[2]), "+f"(d[3])
        : "r"(a0), "r"(a1), "r"(a2), "r"(a3), "r"(b0), "r"(b1));
}

__device__ __forceinline__ void ldsm_x4(uint32_t* r, uint32_t addr) {
    asm volatile("ldmatrix.sync.aligned.m8n8.x4.shared.b16 {%0,%1,%2,%3}, [%4];"
                 : "=r"(r[0]), "=r"(r[1]), "=r"(r[2]), "=r"(r[3]) : "r"(addr));
}

// One 64x128-float A tile (32 KB) -> padded SMEM buffer, 16B cp.async chunks.
// 256 threads: 2048 chunks, 8 per thread.
__device__ __forceinline__ void issue_a(uint32_t sbase, const float* __restrict__ A,
                                        int tile, int tid) {
    const char* g = (const char*)(A + (size_t)tile * (TM * 128));
    #pragma unroll
    for (int j = 0; j < 8; j++) {
        int id = tid + j * 256;            // 2048 chunks of 16 B
        int m  = id >> 5;
        int k4 = id & 31;
        uint32_t soff = sbase + (uint32_t)(m * PAD + k4 * 4) * 4u;
        asm volatile("cp.async.cg.shared.global [%0], [%1], 16;"
                     :: "r"(soff), "l"(g + (size_t)m * 512 + (size_t)k4 * 16)
                     : "memory");
    }
}

__global__ void __launch_bounds__(256, 2)
gemm_kernel(const float* __restrict__ A, float* __restrict__ out, int n_tiles) {
    extern __shared__ float smem[];
    int tid  = threadIdx.x;
    int wid  = tid >> 5;
    int lane = tid & 31;
    int wm   = wid >> 2;          // 0..1 -> 32-row half
    int wn   = wid & 3;           // 0..3 -> 32-col quarter
    int r    = lane >> 2;         // fragment row group 0..7
    int c    = lane & 3;          // fragment col group 0..3

    uint32_t sbase[3];
    sbase[0] = smem_u32(smem);
    sbase[1] = sbase[0] + ABUF_FLTS * 4;
    sbase[2] = sbase[0] + 2 * ABUF_FLTS * 4;

    // ---- pack B fragment sign bits: bw[nf] bit j = sign(B^T[n][c+4j]) ----
    uint32_t bw[4];
    #pragma unroll
    for (int nf = 0; nf < 4; nf++) {
        const float* bp = g_B + (size_t)((wn * 32 + nf * 8 + r) * 128 + c);
        uint32_t w = 0;
        #pragma unroll
        for (int j = 0; j < 32; j++)
            w |= (__float_as_uint(bp[4 * j]) >> 31) << j;
        bw[nf] = w;
    }

    int grid  = (int)gridDim.x;
    int tile0 = (int)blockIdx.x;

    // ---- prologue: fill 3 A buffers ----
    issue_a(sbase[0], A, tile0, tid);
    asm volatile("cp.async.commit_group;" ::: "memory");
    if (tile0 + grid < n_tiles) issue_a(sbase[1], A, tile0 + grid, tid);
    asm volatile("cp.async.commit_group;" ::: "memory");
    if (tile0 + 2 * grid < n_tiles) issue_a(sbase[2], A, tile0 + 2 * grid, tid);
    asm volatile("cp.async.commit_group;" ::: "memory");

    // ldmatrix lane address (byte offset within an A buffer):
    // block j of x4: rows wm*32 + mf*16 + (j&1)*8 + (lane&7), col (j>>1)*4 floats
    uint32_t arow = (uint32_t)(wm * 32 + ((lane >> 3) & 1) * 8 + (lane & 7));
    uint32_t aoff = (arow * PAD + (uint32_t)((lane >> 4) * 4)) * 4u;

    int it = 0;
    for (int tile = tile0; tile < n_tiles; tile += grid, it++) {
        uint32_t abase = sbase[it % 3];

        asm volatile("cp.async.wait_group 2;" ::: "memory");
        __syncthreads();

        float acc[2][4][4];
        #pragma unroll
        for (int mf = 0; mf < 2; mf++)
            #pragma unroll
            for (int nf = 0; nf < 4; nf++)
                #pragma unroll
                for (int q = 0; q < 4; q++) acc[mf][nf][q] = 0.0f;

        uint32_t addr0 = abase + aoff;                  // mf = 0
        uint32_t addr1 = addr0 + 16u * PAD * 4u;        // mf = 1

        #pragma unroll
        for (int q = 0; q < 16; q++) {                  // k0 = 8q
            uint32_t a0[4], a1[4];
            ldsm_x4(a0, addr0 + (uint32_t)q * 32u);
            ldsm_x4(a1, addr1 + (uint32_t)q * 32u);
            #pragma unroll
            for (int t = 0; t < 4; t++) { a0[t] = f2tf32(a0[t]); a1[t] = f2tf32(a1[t]); }

            #pragma unroll
            for (int nf = 0; nf < 4; nf++) {
                uint32_t b0 = 0x3F800000u | ((bw[nf] << (31 - 2 * q)) & 0x80000000u);
                uint32_t b1 = 0x3F800000u | ((bw[nf] << (30 - 2 * q)) & 0x80000000u);
                mma_tf32(acc[0][nf], a0[0], a0[1], a0[2], a0[3], b0, b1);
                mma_tf32(acc[1][nf], a1[0], a1[1], a1[2], a1[3], b0, b1);
            }
        }

        __syncthreads();   // all warps done reading this A buffer

        int nt = tile + 3 * grid;
        if (nt < n_tiles) issue_a(abase, A, nt, tid);
        asm volatile("cp.async.commit_group;" ::: "memory");

        // ---- epilogue: streaming stores ----
        float* obase = out + ((size_t)tile * TM + (size_t)(wm * 32)) * 128 + wn * 32;
        #pragma unroll
        for (int mf = 0; mf < 2; mf++) {
            #pragma unroll
            for (int nf = 0; nf < 4; nf++) {
                float* p = obase + (size_t)(mf * 16 + r) * 128 + nf * 8 + c * 2;
                __stcs((float2*)p,             make_float2(acc[mf][nf][0], acc[mf][nf][1]));
                __stcs((float2*)(p + 8 * 128), make_float2(acc[mf][nf][2], acc[mf][nf][3]));
            }
        }
    }
}

// ------------------------------ launch -------------------------------------

extern "C" void kernel_launch(void* const* d_in, const int* in_sizes, int n_in,
                              void* d_out, int out_size) {
    const float* A       = (const float*)d_in[0];
    const float* W       = (const float*)d_in[1];
    const int*   seed    = (const int*)d_in[2];
    const int*   istrain = (const int*)d_in[3];
    float* out = (float*)d_out;

    int N = in_sizes[0] / 128;
    int n_tiles = N / TM;                  // 16384

    wbin_kernel<<<64, 256>>>(W, seed, istrain);

    int sms = 148;
    cudaDeviceGetAttribute(&sms, cudaDevAttrMultiProcessorCount, 0);
    int grid = 2 * sms;                    // 2 CTAs per SM
    if (grid > n_tiles) grid = n_tiles;

    cudaFuncSetAttribute(gemm_kernel, cudaFuncAttributeMaxDynamicSharedMemorySize, SMEM_TOTAL);
    gemm_kernel<<<grid, 256, SMEM_TOTAL>>>(A, out, n_tiles);
}